// round 3
// baseline (speedup 1.0000x reference)
#include <cuda_runtime.h>

// GatedRecurrentUnitScratch_44908178047583
//
// Exact reduction of the reference:
//   h_new = z * h * (1 - z) * c   with h0 = 0  ==>  h_t == 0 for all t (exact, fp32 too)
//   y = h_hist @ Wy.T + by == broadcast(by) over T=4096 rows
//
// So the kernel is a pure broadcast of by (d_in[11], 512 floats) into the
// [T, 512] output. Memory-bound: 8 MiB of stores, ~2 KB of L2-hit reads.

#define OUT_COLS   512
#define OUT_COLS4  (OUT_COLS / 4)   // 128 float4 per output row

__global__ void GatedRecurrentUnitScratch_44908178047583_kernel(
    const float4* __restrict__ by4,   // [128] float4 = by[512]
    float4* __restrict__ out4,        // [T*128] float4
    int n4)
{
    int i = blockIdx.x * blockDim.x + threadIdx.x;
    if (i < n4) {
        // column within the row; by4 is tiny and stays L1/L2 resident
        out4[i] = __ldg(&by4[i & (OUT_COLS4 - 1)]);
    }
}

extern "C" void kernel_launch(void* const* d_in, const int* in_sizes, int n_in,
                              void* d_out, int out_size)
{
    // metadata order: x, Wx_reset, Wh_reset, b_reset, Wx_candidate, Wh_candidate,
    //                 b_candidate, Wx_update, Wh_update, bh_update, Wy, by
    const float* by = (const float*)d_in[11];

    int n4 = out_size / 4;                 // out_size = 4096*512 = 2097152 -> 524288 float4
    const int threads = 256;
    int blocks = (n4 + threads - 1) / threads;

    GatedRecurrentUnitScratch_44908178047583_kernel<<<blocks, threads>>>(
        (const float4*)by, (float4*)d_out, n4);
}